// round 17
// baseline (speedup 1.0000x reference)
#include <cuda_runtime.h>
#include <cuda_bf16.h>

// Problem dims
#define BB    32
#define SS    512
#define WIN   5
#define EMB   300
#define HH    300
#define K1    1500        // EMB*WIN
#define NOUT  128
#define MROWS (BB*SS)     // 16384

#define NG    16          // persistent GEMM-role blocks in mega kernel

// ------------------------------------------------------------------
// Scratch (static device globals; zero-initialized => tag 0 != 1)
// ------------------------------------------------------------------
__device__ float g_XE[(size_t)MROWS * K1];                // relu(embedded)
__device__ unsigned long long g_AT[(size_t)MROWS * HH];   // {A1, tag=1} tagged
__device__ float g_H1[(size_t)MROWS * HH];                // layer1 hidden states
__device__ float g_H2[(size_t)MROWS * HH];                // layer2 hidden states

// ------------------------------------------------------------------
// helpers
// ------------------------------------------------------------------
__device__ __forceinline__ void ffma2(unsigned long long &d,
                                      unsigned long long a,
                                      unsigned long long b) {
    asm("fma.rn.f32x2 %0, %1, %2, %0;" : "+l"(d) : "l"(a), "l"(b));
}
__device__ __forceinline__ unsigned long long pack2(float lo, float hi) {
    unsigned long long r;
    asm("mov.b64 %0, {%1, %2};" : "=l"(r) : "f"(lo), "f"(hi));
    return r;
}
__device__ __forceinline__ void unpack2(unsigned long long v, float &lo, float &hi) {
    asm("mov.b64 {%0, %1}, %2;" : "=f"(lo), "=f"(hi) : "l"(v));
}
__device__ __forceinline__ unsigned smem_u32(const void *p) {
    unsigned a;
    asm("{ .reg .u64 t; cvta.to.shared.u64 t, %1; cvt.u32.u64 %0, t; }"
        : "=r"(a) : "l"(p));
    return a;
}
__device__ __forceinline__ unsigned long long ldg_rlx(const unsigned long long *p) {
    unsigned long long v;
    asm volatile("ld.relaxed.gpu.global.b64 %0, [%1];" : "=l"(v) : "l"(p) : "memory");
    return v;
}
__device__ __forceinline__ void stg_rlx(unsigned long long *p, unsigned long long v) {
    asm volatile("st.relaxed.gpu.global.b64 [%0], %1;" :: "l"(p), "l"(v) : "memory");
}
__device__ __forceinline__ unsigned long long make_msg(float f, unsigned tag) {
    unsigned long long m;
    asm("mov.b64 %0, {%1, %2};" : "=l"(m) : "r"(__float_as_uint(f)), "r"(tag));
    return m;
}
// tanh via MUFU: 1 - 2/(exp2(2x*log2e)+1). abs err ~1e-7, no division.
__device__ __forceinline__ float tanh_fast(float x) {
    float e;
    asm("ex2.approx.f32 %0, %1;" : "=f"(e) : "f"(x * 2.88539008177792681f));
    float r;
    asm("rcp.approx.f32 %0, %1;" : "=f"(r) : "f"(e + 1.0f));
    return fmaf(-2.0f, r, 1.0f);
}

// ------------------------------------------------------------------
// Kernel 1: embedding gather + relu
// ------------------------------------------------------------------
__global__ void embed_kernel(const int *__restrict__ x,
                             const float *__restrict__ emb) {
    int m = blockIdx.x;            // m = s*32 + b
    int s = m >> 5, b = m & 31;
    __shared__ int idx[WIN];
    if (threadIdx.x < WIN) idx[threadIdx.x] = x[(b * SS + s) * WIN + threadIdx.x];
    __syncthreads();
    float4 *out4 = reinterpret_cast<float4 *>(g_XE + (size_t)m * K1);
    for (int i = threadIdx.x; i < K1 / 4; i += blockDim.x) {
        int e4 = i * 4;
        int w = e4 / EMB;
        int e = e4 - w * EMB;
        float4 v = *reinterpret_cast<const float4 *>(emb + (size_t)idx[w] * EMB + e);
        v.x = fmaxf(v.x, 0.f); v.y = fmaxf(v.y, 0.f);
        v.z = fmaxf(v.z, 0.f); v.w = fmaxf(v.w, 0.f);
        out4[i] = v;
    }
}

// ------------------------------------------------------------------
// GEMM (proven R8): BM=128, BN=128, BK=16, 256 thr, 8x8 tile, dbl-buffered.
// Used for the two output projections (PERM store).
// ------------------------------------------------------------------
template <bool PERM>
__global__ __launch_bounds__(256)
void gemm_nt(const float *__restrict__ A, const float *__restrict__ Bw,
             const float *__restrict__ b1, const float *__restrict__ b2,
             float *__restrict__ C, int M, int N, int K, int ldc) {
    __shared__ __align__(16) float As[2][16][132];
    __shared__ __align__(16) float Bs[2][16][132];

    const int tid = threadIdx.x;
    const int m0 = blockIdx.y * 128;
    const int n0 = blockIdx.x * 128;
    const int tx = tid & 15;
    const int ty = tid >> 4;
    const int lr = tid >> 1;
    const int lk = (tid & 1) * 8;

    unsigned long long acc[8][4];
#pragma unroll
    for (int i = 0; i < 8; i++)
#pragma unroll
        for (int j = 0; j < 4; j++) acc[i][j] = 0ULL;

    const int KT = (K + 15) >> 4;

    {
        float4 a0 = make_float4(0.f,0.f,0.f,0.f), a1 = a0, v0 = a0, v1 = a0;
        int kk = lk;
        const float *ap = A + (size_t)(m0 + lr) * K;
        if (kk     < K) a0 = *reinterpret_cast<const float4 *>(ap + kk);
        if (kk + 4 < K) a1 = *reinterpret_cast<const float4 *>(ap + kk + 4);
        if (n0 + lr < N) {
            const float *bp = Bw + (size_t)(n0 + lr) * K;
            if (kk     < K) v0 = *reinterpret_cast<const float4 *>(bp + kk);
            if (kk + 4 < K) v1 = *reinterpret_cast<const float4 *>(bp + kk + 4);
        }
        As[0][lk+0][lr]=a0.x; As[0][lk+1][lr]=a0.y; As[0][lk+2][lr]=a0.z; As[0][lk+3][lr]=a0.w;
        As[0][lk+4][lr]=a1.x; As[0][lk+5][lr]=a1.y; As[0][lk+6][lr]=a1.z; As[0][lk+7][lr]=a1.w;
        Bs[0][lk+0][lr]=v0.x; Bs[0][lk+1][lr]=v0.y; Bs[0][lk+2][lr]=v0.z; Bs[0][lk+3][lr]=v0.w;
        Bs[0][lk+4][lr]=v1.x; Bs[0][lk+5][lr]=v1.y; Bs[0][lk+6][lr]=v1.z; Bs[0][lk+7][lr]=v1.w;
    }
    __syncthreads();

    for (int kt = 0; kt < KT; kt++) {
        const int cb = kt & 1;
        float4 a0 = make_float4(0.f,0.f,0.f,0.f), a1 = a0, v0 = a0, v1 = a0;
        const bool more = (kt + 1 < KT);
        if (more) {
            int kk = (kt + 1) * 16 + lk;
            const float *ap = A + (size_t)(m0 + lr) * K;
            if (kk     < K) a0 = *reinterpret_cast<const float4 *>(ap + kk);
            if (kk + 4 < K) a1 = *reinterpret_cast<const float4 *>(ap + kk + 4);
            if (n0 + lr < N) {
                const float *bp = Bw + (size_t)(n0 + lr) * K;
                if (kk     < K) v0 = *reinterpret_cast<const float4 *>(bp + kk);
                if (kk + 4 < K) v1 = *reinterpret_cast<const float4 *>(bp + kk + 4);
            }
        }

#pragma unroll
        for (int k = 0; k < 16; k++) {
            float4 aA = *reinterpret_cast<const float4 *>(&As[cb][k][ty * 8]);
            float4 aB = *reinterpret_cast<const float4 *>(&As[cb][k][ty * 8 + 4]);
            ulonglong2 bA = *reinterpret_cast<const ulonglong2 *>(&Bs[cb][k][tx * 8]);
            ulonglong2 bB = *reinterpret_cast<const ulonglong2 *>(&Bs[cb][k][tx * 8 + 4]);
            unsigned long long p0 = pack2(aA.x, aA.x), p1 = pack2(aA.y, aA.y);
            unsigned long long p2 = pack2(aA.z, aA.z), p3 = pack2(aA.w, aA.w);
            unsigned long long p4 = pack2(aB.x, aB.x), p5 = pack2(aB.y, aB.y);
            unsigned long long p6 = pack2(aB.z, aB.z), p7 = pack2(aB.w, aB.w);
            ffma2(acc[0][0], p0, bA.x); ffma2(acc[0][1], p0, bA.y);
            ffma2(acc[0][2], p0, bB.x); ffma2(acc[0][3], p0, bB.y);
            ffma2(acc[1][0], p1, bA.x); ffma2(acc[1][1], p1, bA.y);
            ffma2(acc[1][2], p1, bB.x); ffma2(acc[1][3], p1, bB.y);
            ffma2(acc[2][0], p2, bA.x); ffma2(acc[2][1], p2, bA.y);
            ffma2(acc[2][2], p2, bB.x); ffma2(acc[2][3], p2, bB.y);
            ffma2(acc[3][0], p3, bA.x); ffma2(acc[3][1], p3, bA.y);
            ffma2(acc[3][2], p3, bB.x); ffma2(acc[3][3], p3, bB.y);
            ffma2(acc[4][0], p4, bA.x); ffma2(acc[4][1], p4, bA.y);
            ffma2(acc[4][2], p4, bB.x); ffma2(acc[4][3], p4, bB.y);
            ffma2(acc[5][0], p5, bA.x); ffma2(acc[5][1], p5, bA.y);
            ffma2(acc[5][2], p5, bB.x); ffma2(acc[5][3], p5, bB.y);
            ffma2(acc[6][0], p6, bA.x); ffma2(acc[6][1], p6, bA.y);
            ffma2(acc[6][2], p6, bB.x); ffma2(acc[6][3], p6, bB.y);
            ffma2(acc[7][0], p7, bA.x); ffma2(acc[7][1], p7, bA.y);
            ffma2(acc[7][2], p7, bB.x); ffma2(acc[7][3], p7, bB.y);
        }

        if (more) {
            const int nb = cb ^ 1;
            As[nb][lk+0][lr]=a0.x; As[nb][lk+1][lr]=a0.y; As[nb][lk+2][lr]=a0.z; As[nb][lk+3][lr]=a0.w;
            As[nb][lk+4][lr]=a1.x; As[nb][lk+5][lr]=a1.y; As[nb][lk+6][lr]=a1.z; As[nb][lk+7][lr]=a1.w;
            Bs[nb][lk+0][lr]=v0.x; Bs[nb][lk+1][lr]=v0.y; Bs[nb][lk+2][lr]=v0.z; Bs[nb][lk+3][lr]=v0.w;
            Bs[nb][lk+4][lr]=v1.x; Bs[nb][lk+5][lr]=v1.y; Bs[nb][lk+6][lr]=v1.z; Bs[nb][lk+7][lr]=v1.w;
        }
        __syncthreads();
    }

    float bias[8];
#pragma unroll
    for (int jj = 0; jj < 8; jj++) {
        int n = n0 + tx * 8 + jj;
        bias[jj] = (n < N) ? (b1[n] + (b2 ? b2[n] : 0.f)) : 0.f;
    }
    const int nbase = n0 + tx * 8;
    const bool full = (nbase + 8 <= N);
#pragma unroll
    for (int i = 0; i < 8; i++) {
        int m = m0 + ty * 8 + i;
        int row = PERM ? ((m & 31) * SS + (m >> 5)) : m;
        float *cp = C + (size_t)row * ldc;
        float v[8];
#pragma unroll
        for (int j = 0; j < 4; j++) {
            float lo, hi;
            unpack2(acc[i][j], lo, hi);
            v[2*j]   = lo + bias[2*j];
            v[2*j+1] = hi + bias[2*j+1];
        }
        if (full) {
            *reinterpret_cast<float4 *>(cp + nbase)     = make_float4(v[0], v[1], v[2], v[3]);
            *reinterpret_cast<float4 *>(cp + nbase + 4) = make_float4(v[4], v[5], v[6], v[7]);
        } else {
#pragma unroll
            for (int j = 0; j < 8; j++)
                if (nbase + j < N) cp[nbase + j] = v[j];
        }
    }
}

// ------------------------------------------------------------------
// MEGA kernel: 144 blocks (36 x 4-CTA clusters, all wave-1 resident).
//   blocks 0..127  : R16-champion fused recurrence (A1 read as tagged u64)
//   blocks 128..143: persistent GEMM role, A1 = XE @ W_ih1^T + bias,
//                    tiles in ascending-m order, tagged {f32,1} stores.
// rec's fin1 polls the tag only at consumption; producer stays ahead
// (one 4-timestep m-tile per ~8.3us vs rec's ~10us consumption).
// ------------------------------------------------------------------
#define OFF_W    0
#define OFF_H1   91200
#define OFF_H2   91840
#define OFF_IB1  92480
#define OFF_IB2  97344
#define REC_SMEM 102208

__global__ void __cluster_dims__(4, 1, 1) __launch_bounds__(320, 1)
mega_kernel(const float *__restrict__ Whh1, const float *__restrict__ Wih2,
            const float *__restrict__ Whh2, const float *__restrict__ bih2,
            const float *__restrict__ bhh2, const float *__restrict__ Wih1,
            const float *__restrict__ bih1, const float *__restrict__ bhh1,
            float *__restrict__ H1out, float *__restrict__ H2out) {
    extern __shared__ __align__(32) char smem[];
    const int bid = blockIdx.x;
    const int tid = threadIdx.x;

    if (bid < 128) {
        // ==================== recurrence role (R16 champion) ====================
        float *h1loc = reinterpret_cast<float *>(smem + OFF_H1);           // [2][80]
        float *h2loc = reinterpret_cast<float *>(smem + OFF_H2);           // [2][80]
        unsigned long long *ib1 = reinterpret_cast<unsigned long long *>(smem + OFF_IB1);
        unsigned long long *ib2 = reinterpret_cast<unsigned long long *>(smem + OFF_IB2);

        const int rank = bid & 3;
        const int b    = bid >> 2;
        const bool active = tid < 300;
        const int dst  = active ? (tid / 75) : 0;
        const int slot = active ? (tid % 75) : 0;
        const bool self_dst = active && (dst == rank);

        unsigned long long w1[38], wi[38];
        if (active) {
            const float *p1 = Whh1 + (size_t)tid * HH + rank * 75;
            const float *p2 = Wih2 + (size_t)tid * HH + rank * 75;
#pragma unroll
            for (int i = 0; i < 37; i++) {
                w1[i] = pack2(p1[2 * i], p1[2 * i + 1]);
                wi[i] = pack2(p2[2 * i], p2[2 * i + 1]);
            }
            w1[37] = pack2(p1[74], 0.f);
            wi[37] = pack2(p2[74], 0.f);
        }
        {
            float4 *Ws = reinterpret_cast<float4 *>(smem + OFF_W);
            for (int e = tid; e < 19 * 300; e += 320) {
                int q = e / 300, j = e - q * 300;
                const float *wp = Whh2 + (size_t)j * HH + rank * 75 + 4 * q;
                int c0 = 4 * q;
                float4 v;
                v.x = (c0 + 0 < 75) ? wp[0] : 0.f;
                v.y = (c0 + 1 < 75) ? wp[1] : 0.f;
                v.z = (c0 + 2 < 75) ? wp[2] : 0.f;
                v.w = (c0 + 3 < 75) ? wp[3] : 0.f;
                Ws[e] = v;
            }
        }
        for (int i = tid; i < 2 * 80; i += 320) { h1loc[i] = 0.f; h2loc[i] = 0.f; }
        for (int i = tid; i < 2 * 76 * 4; i += 320) {
            ib1[i] = 0xFFFFFFFF00000000ULL;
            ib2[i] = 0xFFFFFFFF00000000ULL;
        }
        __syncthreads();
        asm volatile("barrier.cluster.arrive.aligned;" ::: "memory");
        asm volatile("barrier.cluster.wait.aligned;" ::: "memory");

        unsigned in1_rem[2], in2_rem[2];
        volatile unsigned long long *in1_loc[2], *in2_loc[2];
        if (active) {
#pragma unroll
            for (int p = 0; p < 2; p++) {
                int idx = (p * 76 + slot) * 4 + rank;
                unsigned l1 = smem_u32(&ib1[idx]);
                unsigned l2 = smem_u32(&ib2[idx]);
                asm("mapa.shared::cluster.u32 %0, %1, %2;" : "=r"(in1_rem[p]) : "r"(l1), "r"(dst));
                asm("mapa.shared::cluster.u32 %0, %1, %2;" : "=r"(in2_rem[p]) : "r"(l2), "r"(dst));
                in1_loc[p] = &ib1[idx];
                in2_loc[p] = &ib2[idx];
            }
        }
        const bool fin1 = active && (dst == rank);
        const int  sl1  = slot;
        const int  r2   = (rank + 2) & 3;
        const bool fin2 = active && (dst == r2);
        const int  sl2  = slot;
        unsigned poll1[2], poll2[2];
        if (fin1) {
#pragma unroll
            for (int p = 0; p < 2; p++)
                poll1[p] = smem_u32(&ib1[(p * 76 + sl1) * 4]);
        }
        float bias2 = 0.f;
        if (fin2) {
#pragma unroll
            for (int p = 0; p < 2; p++)
                poll2[p] = smem_u32(&ib2[(p * 76 + sl2) * 4]);
            int row = 75 * rank + sl2;
            bias2 = bih2[row] + bhh2[row];
        }

        const unsigned long long *aTrow = g_AT + (size_t)b * HH + rank * 75 + sl1;
        float *h1row = H1out + (size_t)b * HH + rank * 75;
        float *h2row = H2out + (size_t)b * HH + rank * 75;
        const ulonglong2 *Ws2 = reinterpret_cast<const ulonglong2 *>(smem + OFF_W);

        unsigned long long a_cur = fin1 ? ldg_rlx(aTrow) : 0ULL;  // speculative

        for (int t = 0; t <= SS; t++) {
            const int pb = t & 1;
            unsigned long long a_nxt = 0ULL;
            if (fin1 && t + 1 < SS)
                a_nxt = ldg_rlx(aTrow + (size_t)(t + 1) * BB * HH);  // speculative

            if (active) {
                const ulonglong2 *hp1 =
                    reinterpret_cast<const ulonglong2 *>(&h1loc[(pb ^ 1) * 80]);
                const ulonglong2 *hp2 =
                    reinterpret_cast<const ulonglong2 *>(&h2loc[pb * 80]);   // h2_{t-2}
                unsigned long long c0 = 0, c1 = 0, d0 = 0, d1 = 0, e0 = 0, e1 = 0;
#pragma unroll
                for (int k = 0; k < 19; k++) {
                    ulonglong2 hv = hp1[k];
                    ffma2(c0, w1[2 * k], hv.x); ffma2(c1, w1[2 * k + 1], hv.y);
                    ffma2(d0, wi[2 * k], hv.x); ffma2(d1, wi[2 * k + 1], hv.y);
                    ulonglong2 wv = Ws2[k * 300 + tid];
                    ulonglong2 h2v = hp2[k];
                    ffma2(e0, wv.x, h2v.x); ffma2(e1, wv.y, h2v.y);
                }
                float x0, x1, y0, y1;
                unpack2(c0, x0, x1); unpack2(c1, y0, y1);
                float p1v = (x0 + x1) + (y0 + y1);
                unpack2(d0, x0, x1); unpack2(d1, y0, y1);
                float piv = (x0 + x1) + (y0 + y1);
                unpack2(e0, x0, x1); unpack2(e1, y0, y1);
                float p2v = piv + (x0 + x1) + (y0 + y1);

                if (t < SS) {
                    unsigned long long msg;
                    asm("mov.b64 %0, {%1, %2};"
                        : "=l"(msg) : "r"(__float_as_uint(p1v)), "r"((unsigned)t));
                    if (self_dst) {
                        *in1_loc[pb] = msg;
                    } else {
                        asm volatile("st.relaxed.cluster.shared::cluster.b64 [%0], %1;"
                                     :: "r"(in1_rem[pb]), "l"(msg) : "memory");
                    }
                }
                if (t >= 1) {
                    unsigned long long msg;
                    asm("mov.b64 %0, {%1, %2};"
                        : "=l"(msg) : "r"(__float_as_uint(p2v)), "r"((unsigned)t));
                    if (self_dst) {
                        *in2_loc[pb] = msg;
                    } else {
                        asm volatile("st.relaxed.cluster.shared::cluster.b64 [%0], %1;"
                                     :: "r"(in2_rem[pb]), "l"(msg) : "memory");
                    }
                }
            }

            if (fin1 && t < SS) {
                // validate speculative A1 read (tag==1 means GEMM role wrote it)
                unsigned long long av = a_cur;
                {
                    const unsigned long long *ap = aTrow + (size_t)t * BB * HH;
                    while ((unsigned)(av >> 32) != 1u) av = ldg_rlx(ap);
                }
                const unsigned want = (unsigned)t;
                unsigned long long v0, v1, v2, v3;
                do {
                    asm volatile("ld.volatile.shared.v2.u64 {%0,%1}, [%2];"
                                 : "=l"(v0), "=l"(v1) : "r"(poll1[pb]) : "memory");
                    asm volatile("ld.volatile.shared.v2.u64 {%0,%1}, [%2];"
                                 : "=l"(v2), "=l"(v3) : "r"(poll1[pb] + 16) : "memory");
                } while (((unsigned)(v0 >> 32) != want) | ((unsigned)(v1 >> 32) != want) |
                         ((unsigned)(v2 >> 32) != want) | ((unsigned)(v3 >> 32) != want));
                float s = __uint_as_float((unsigned)av)
                        + __uint_as_float((unsigned)v0)
                        + __uint_as_float((unsigned)v1)
                        + __uint_as_float((unsigned)v2)
                        + __uint_as_float((unsigned)v3);
                float hv = tanh_fast(s);
                h1row[(size_t)t * BB * HH + sl1] = hv;
                h1loc[pb * 80 + sl1] = hv;
            }
            if (fin2 && t >= 1) {
                const unsigned want = (unsigned)t;
                unsigned long long v0, v1, v2, v3;
                do {
                    asm volatile("ld.volatile.shared.v2.u64 {%0,%1}, [%2];"
                                 : "=l"(v0), "=l"(v1) : "r"(poll2[pb]) : "memory");
                    asm volatile("ld.volatile.shared.v2.u64 {%0,%1}, [%2];"
                                 : "=l"(v2), "=l"(v3) : "r"(poll2[pb] + 16) : "memory");
                } while (((unsigned)(v0 >> 32) != want) | ((unsigned)(v1 >> 32) != want) |
                         ((unsigned)(v2 >> 32) != want) | ((unsigned)(v3 >> 32) != want));
                float s = bias2 + __uint_as_float((unsigned)v0)
                                + __uint_as_float((unsigned)v1)
                                + __uint_as_float((unsigned)v2)
                                + __uint_as_float((unsigned)v3);
                float hv = tanh_fast(s);
                h2row[(size_t)(t - 1) * BB * HH + sl2] = hv;
                h2loc[(pb ^ 1) * 80 + sl2] = hv;
            }
            a_cur = a_nxt;
            __syncthreads();
        }

        asm volatile("barrier.cluster.arrive.aligned;" ::: "memory");
        asm volatile("barrier.cluster.wait.aligned;" ::: "memory");

    } else {
        // ==================== persistent GEMM role ====================
        // A1[m][n] = XE[m] . Wih1[n] + bih1[n] + bhh1[n], tagged stores.
        // 384 tasks (mt=T/3 ascending => ascending-m completion).
        const int gid = bid - 128;
        float (*As)[132] = reinterpret_cast<float(*)[132]>(smem);
        float (*Bs)[132] = reinterpret_cast<float(*)[132]>(smem + 16 * 132 * 4);

        const int tx = tid & 15;
        const int ty = (tid >> 4) & 15;
        const int lr = (tid >> 1) & 127;
        const int lk = (tid & 1) * 8;
        const bool work = tid < 256;

        for (int T = gid; T < 384; T += NG) {
            const int mt = T / 3, nt = T - 3 * mt;
            const int m0 = mt * 128, n0 = nt * 128;

            unsigned long long acc[8][4];
#pragma unroll
            for (int i = 0; i < 8; i++)
#pragma unroll
                for (int j = 0; j < 4; j++) acc[i][j] = 0ULL;

            for (int kt = 0; kt < 94; kt++) {
                if (work) {
                    int kk = kt * 16 + lk;
                    float4 a0 = make_float4(0.f,0.f,0.f,0.f), a1 = a0, v0 = a0, v1 = a0;
                    const float *ap = g_XE + (size_t)(m0 + lr) * K1;
                    if (kk     < K1) a0 = *reinterpret_cast<const float4 *>(ap + kk);
                    if (kk + 4 < K1) a1 = *reinterpret_cast<const float4 *>(ap + kk + 4);
                    if (n0 + lr < HH) {
                        const float *bp = Wih1 + (size_t)(n0 + lr) * K1;
                        if (kk     < K1) v0 = *reinterpret_cast<const float4 *>(bp + kk);
                        if (kk + 4 < K1) v1 = *reinterpret_cast<const float4 *>(bp + kk + 4);
                    }
                    As[lk+0][lr]=a0.x; As[lk+1][lr]=a0.y; As[lk+2][lr]=a0.z; As[lk+3][lr]=a0.w;
                    As[lk+4][lr]=a1.x; As[lk+5][lr]=a1.y; As[lk+6][lr]=a1.z; As[lk+7][lr]=a1.w;
                    Bs[lk+0][lr]=v0.x; Bs[lk+1][lr]=v0.y; Bs[lk+2][lr]=v0.z; Bs[lk+3][lr]=v0.w;
                    Bs[lk+4][lr]=v1.x; Bs[lk+5][lr]=v1.y; Bs[lk+6][lr]=v1.z; Bs[lk+7][lr]=v1.w;
                }
                __syncthreads();
                if (work) {
#pragma unroll
                    for (int k = 0; k < 16; k++) {
                        float4 aA = *reinterpret_cast<const float4 *>(&As[k][ty * 8]);
                        float4 aB = *reinterpret_cast<const float4 *>(&As[k][ty * 8 + 4]);
                        ulonglong2 bA = *reinterpret_cast<const ulonglong2 *>(&Bs[k][tx * 8]);
                        ulonglong2 bB = *reinterpret_cast<const ulonglong2 *>(&Bs[k][tx * 8 + 4]);
                        unsigned long long p0 = pack2(aA.x, aA.x), p1 = pack2(aA.y, aA.y);
                        unsigned long long p2 = pack2(aA.z, aA.z), p3 = pack2(aA.w, aA.w);
                        unsigned long long p4 = pack2(aB.x, aB.x), p5 = pack2(aB.y, aB.y);
                        unsigned long long p6 = pack2(aB.z, aB.z), p7 = pack2(aB.w, aB.w);
                        ffma2(acc[0][0], p0, bA.x); ffma2(acc[0][1], p0, bA.y);
                        ffma2(acc[0][2], p0, bB.x); ffma2(acc[0][3], p0, bB.y);
                        ffma2(acc[1][0], p1, bA.x); ffma2(acc[1][1], p1, bA.y);
                        ffma2(acc[1][2], p1, bB.x); ffma2(acc[1][3], p1, bB.y);
                        ffma2(acc[2][0], p2, bA.x); ffma2(acc[2][1], p2, bA.y);
                        ffma2(acc[2][2], p2, bB.x); ffma2(acc[2][3], p2, bB.y);
                        ffma2(acc[3][0], p3, bA.x); ffma2(acc[3][1], p3, bA.y);
                        ffma2(acc[3][2], p3, bB.x); ffma2(acc[3][3], p3, bB.y);
                        ffma2(acc[4][0], p4, bA.x); ffma2(acc[4][1], p4, bA.y);
                        ffma2(acc[4][2], p4, bB.x); ffma2(acc[4][3], p4, bB.y);
                        ffma2(acc[5][0], p5, bA.x); ffma2(acc[5][1], p5, bA.y);
                        ffma2(acc[5][2], p5, bB.x); ffma2(acc[5][3], p5, bB.y);
                        ffma2(acc[6][0], p6, bA.x); ffma2(acc[6][1], p6, bA.y);
                        ffma2(acc[6][2], p6, bB.x); ffma2(acc[6][3], p6, bB.y);
                        ffma2(acc[7][0], p7, bA.x); ffma2(acc[7][1], p7, bA.y);
                        ffma2(acc[7][2], p7, bB.x); ffma2(acc[7][3], p7, bB.y);
                    }
                }
                __syncthreads();
            }

            if (work) {
#pragma unroll
                for (int i = 0; i < 8; i++) {
                    const int m = m0 + ty * 8 + i;
                    unsigned long long *op = g_AT + (size_t)m * HH;
#pragma unroll
                    for (int j = 0; j < 4; j++) {
                        float lo, hi;
                        unpack2(acc[i][j], lo, hi);
                        int n = n0 + tx * 8 + 2 * j;
                        if (n < HH)
                            stg_rlx(op + n, make_msg(lo + bih1[n] + bhh1[n], 1u));
                        if (n + 1 < HH)
                            stg_rlx(op + n + 1, make_msg(hi + bih1[n+1] + bhh1[n+1], 1u));
                    }
                }
            }
        }
    }
}

// ------------------------------------------------------------------
// Launch sequence
// ------------------------------------------------------------------
extern "C" void kernel_launch(void *const *d_in, const int *in_sizes, int n_in,
                              void *d_out, int out_size) {
    const int   *x     = (const int *)d_in[0];
    const float *emb   = (const float *)d_in[1];
    const float *W_ih1 = (const float *)d_in[2];
    const float *W_hh1 = (const float *)d_in[3];
    const float *b_ih1 = (const float *)d_in[4];
    const float *b_hh1 = (const float *)d_in[5];
    const float *W_ih2 = (const float *)d_in[6];
    const float *W_hh2 = (const float *)d_in[7];
    const float *b_ih2 = (const float *)d_in[8];
    const float *b_hh2 = (const float *)d_in[9];
    const float *fc1_w = (const float *)d_in[10];
    const float *fc1_b = (const float *)d_in[11];
    const float *fc2_w = (const float *)d_in[12];
    const float *fc2_b = (const float *)d_in[13];
    float *out = (float *)d_out;

    float *h1, *h2;
    cudaGetSymbolAddress((void **)&h1, g_H1);
    cudaGetSymbolAddress((void **)&h2, g_H2);

    static int smem_set = 0;
    if (!smem_set) {
        cudaFuncSetAttribute(mega_kernel,
                             cudaFuncAttributeMaxDynamicSharedMemorySize,
                             REC_SMEM);
        smem_set = 1;
    }

    // 1) embed + relu
    embed_kernel<<<MROWS, 128>>>(x, emb);

    // 2) overlapped A1-GEMM + fused recurrence (one resident kernel)
    mega_kernel<<<144, 320, REC_SMEM>>>(W_hh1, W_ih2, W_hh2, b_ih2, b_hh2,
                                        W_ih1, b_ih1, b_hh1, h1, h2);

    // 3) projections (permuted store: m = s*32+b -> row b*512+s)
    {
        dim3 grid((NOUT + 127) / 128, MROWS / 128);
        gemm_nt<true><<<grid, 256>>>(h1, fc1_w, fc1_b, nullptr, out,
                                     MROWS, NOUT, HH, NOUT);
        gemm_nt<true><<<grid, 256>>>(h2, fc2_w, fc2_b, nullptr,
                                     out + (size_t)MROWS * NOUT,
                                     MROWS, NOUT, HH, NOUT);
    }
}